// round 12
// baseline (speedup 1.0000x reference)
#include <cuda_runtime.h>
#include <math_constants.h>

#define N_NODES 100000
#define MAX_ETOT 3300000   // 3.2M edges + 100k self-loops
#define SCAN_B 1024
#define NSCAN ((N_NODES + SCAN_B - 1) / SCAN_B)   // 98

// ---------------- scratch (device globals; no allocation allowed) ----------
__device__ int      g_is64;
__device__ int      g_src[MAX_ETOT];
__device__ int      g_dst[MAX_ETOT];
__device__ int      g_cnt[N_NODES];
__device__ int      g_row[N_NODES + 1];
__device__ int      g_woff[N_NODES];
__device__ int      g_bsum[NSCAN];
__device__ int      g_ssrc[MAX_ETOT];
__device__ __align__(16) float g_h1 [N_NODES * 64];
__device__ __align__(16) float g_es1[N_NODES * 8];
__device__ __align__(16) float g_ed1[N_NODES * 8];
__device__ __align__(16) float g_x2 [N_NODES * 64];
__device__ __align__(16) float g_h2 [N_NODES * 32];
__device__ float    g_es2[N_NODES];
__device__ float    g_ed2[N_NODES];
__device__ float    g_out2[N_NODES * 32];
__device__ double   g_pool[32];

// ---------------- helpers ----------------
__device__ __forceinline__ float lrelu(float v) { return v > 0.f ? v : 0.2f * v; }
__device__ __forceinline__ int clampN(int v) {
    return v < 0 ? 0 : (v >= N_NODES ? N_NODES - 1 : v);
}
// fast exp on FMA/ALU pipes (no MUFU). rel err ~2.4e-6 over |x| < 88.
__device__ __forceinline__ float fexp(float x) {
    x = fmaxf(fminf(x, 80.f), -80.f);
    float y = x * 1.4426950408889634f;     // log2(e)
    float fl = rintf(y);
    float f = y - fl;                      // f in [-0.5, 0.5]
    int   i = (int)fl;
    float p =            1.3333558146428443e-3f;
    p = fmaf(p, f, 9.618129107628477e-3f);
    p = fmaf(p, f, 5.550410866482158e-2f);
    p = fmaf(p, f, 2.402265069591007e-1f);
    p = fmaf(p, f, 6.931471805599453e-1f);
    p = fmaf(p, f, 1.0f);
    return __int_as_float((i + 127) << 23) * p;
}

// ---------------- dtype sniff ----------------
__global__ void k_detect(const int* __restrict__ e) {
    __shared__ int any;
    if (threadIdx.x == 0) any = 0;
    __syncthreads();
    int acc = 0;
    for (int i = 2 * threadIdx.x + 1; i < 4096; i += 2 * blockDim.x) acc |= e[i];
    if (acc) atomicOr(&any, 1);
    __syncthreads();
    if (threadIdx.x == 0) g_is64 = (any == 0) ? 1 : 0;
}

// ---------------- init (before k_edges: histogram fused there) ------------
__global__ void __launch_bounds__(256) k_init() {
    int j = blockIdx.x * blockDim.x + threadIdx.x;
    if (j < N_NODES) g_cnt[j] = 0;
    if (j < 32)      g_pool[j] = 0.0;
}

// -------- prep: edges -> int32, self-loops appended, degree histogram -----
__global__ void __launch_bounds__(256) k_edges(const void* __restrict__ eraw,
                                               int E, int Etot) {
    int i = blockIdx.x * blockDim.x + threadIdx.x;
    if (i >= Etot) return;
    int s, d;
    if (i >= E) { s = i - E; d = s; }
    else if (g_is64) {
        const long long* e64 = (const long long*)eraw;
        s = clampN((int)e64[i]);
        d = clampN((int)e64[E + i]);
    } else {
        const int* e32 = (const int*)eraw;
        s = clampN(e32[i]);
        d = clampN(e32[E + i]);
    }
    g_src[i] = s;
    g_dst[i] = d;
    atomicAdd(&g_cnt[d], 1);
}

// ---------------- CSR build ----------------
__global__ void __launch_bounds__(SCAN_B) k_scan1() {
    __shared__ int sh[SCAN_B];
    int t = threadIdx.x;
    int i = blockIdx.x * SCAN_B + t;
    int v = (i < N_NODES) ? g_cnt[i] : 0;
    sh[t] = v;
    __syncthreads();
    for (int o = 1; o < SCAN_B; o <<= 1) {
        int x = (t >= o) ? sh[t - o] : 0;
        __syncthreads();
        sh[t] += x;
        __syncthreads();
    }
    if (i < N_NODES) g_row[i] = sh[t] - v;
    if (t == SCAN_B - 1) g_bsum[blockIdx.x] = sh[t];
}

__global__ void __launch_bounds__(128) k_scan2() {
    __shared__ int sh[128];
    int t = threadIdx.x;
    int v = (t < NSCAN) ? g_bsum[t] : 0;
    sh[t] = v;
    __syncthreads();
    for (int o = 1; o < 128; o <<= 1) {
        int x = (t >= o) ? sh[t - o] : 0;
        __syncthreads();
        sh[t] += x;
        __syncthreads();
    }
    if (t < NSCAN) g_bsum[t] = sh[t] - v;
}

__global__ void __launch_bounds__(256) k_scan3(int Etot) {
    int i = blockIdx.x * blockDim.x + threadIdx.x;
    if (i < N_NODES) {
        int r = g_row[i] + g_bsum[i / SCAN_B];
        g_row[i] = r;
        g_woff[i] = r;
    }
    if (i == 0) g_row[N_NODES] = Etot;
}

__global__ void __launch_bounds__(256) k_scatter(int Etot) {
    int i = blockIdx.x * blockDim.x + threadIdx.x;
    if (i >= Etot) return;
    int pos = atomicAdd(&g_woff[g_dst[i]], 1);
    g_ssrc[pos] = g_src[i];
}

// ---------------- GEMM1: h1 = x[N,128] @ W1[128,64] ----------------
__global__ void __launch_bounds__(256) k_gemm1(const float* __restrict__ x,
                                               const float* __restrict__ W) {
    __shared__ __align__(16) float sW[128 * 64];
    __shared__ __align__(16) float sx[16 * 128];
    int t = threadIdx.x;                      // 256 threads, 16 nodes/block
    const float4* W4 = (const float4*)W;
    float4* sW4 = (float4*)sW;
#pragma unroll
    for (int i = 0; i < 8; i++) sW4[t + i * 256] = W4[t + i * 256];
    const float4* x4 = (const float4*)(x + (size_t)blockIdx.x * 16 * 128);
    float4* sx4 = (float4*)sx;
#pragma unroll
    for (int i = 0; i < 2; i++) sx4[t + i * 256] = x4[t + i * 256];
    __syncthreads();
    int ln = t >> 4, g = t & 15;
    float4 acc = make_float4(0.f, 0.f, 0.f, 0.f);
    const float* xr = sx + ln * 128;
#pragma unroll 8
    for (int k = 0; k < 128; k++) {
        float xv = xr[k];
        float4 w = *(const float4*)&sW[k * 64 + g * 4];
        acc.x += xv * w.x; acc.y += xv * w.y; acc.z += xv * w.z; acc.w += xv * w.w;
    }
    *(float4*)&g_h1[(size_t)(blockIdx.x * 16 + ln) * 64 + g * 4] = acc;
}

// ---------------- e_src/e_dst layer 1 ----------------
__global__ void __launch_bounds__(256) k_e1(const float* __restrict__ as,
                                            const float* __restrict__ ad) {
    int i = blockIdx.x * blockDim.x + threadIdx.x;
    if (i >= N_NODES * 8) return;
    int n = i >> 3, h = i & 7;
    float s = 0.f, d = 0.f;
#pragma unroll
    for (int j = 0; j < 8; j++) {
        float hv = g_h1[(size_t)n * 64 + h * 8 + j];
        s += hv * as[h * 8 + j];
        d += hv * ad[h * 8 + j];
    }
    g_es1[i] = s;
    g_ed1[i] = d;
}

// ---- layer-1 FUSED softmax+aggregation: one edge pass, no scratch --------
// warp per dst; lanes 0-7 own heads (alpha+denominator), all lanes features
__global__ void __launch_bounds__(256) k_agg1f() {
    int d = (blockIdx.x * blockDim.x + threadIdx.x) >> 5;
    int lane = threadIdx.x & 31;
    if (d >= N_NODES) return;
    int beg = g_row[d], end = g_row[d + 1];
    float edh = (lane < 8) ? g_ed1[d * 8 + lane] : 0.f;
    float den = 0.f, acc0 = 0.f, acc1 = 0.f;
#pragma unroll 2
    for (int e = beg; e < end; e++) {
        int s = g_ssrc[e];
        float al = 0.f;
        if (lane < 8) {
            al = fexp(lrelu(g_es1[s * 8 + lane] + edh));
            den += al;
        }
        float a0 = __shfl_sync(0xffffffffu, al, lane >> 3);
        float a1 = __shfl_sync(0xffffffffu, al, (lane >> 3) + 4);
        acc0 += a0 * g_h1[(size_t)s * 64 + lane];
        acc1 += a1 * g_h1[(size_t)s * 64 + 32 + lane];
    }
    float d0 = __shfl_sync(0xffffffffu, den, lane >> 3);
    float d1 = __shfl_sync(0xffffffffu, den, (lane >> 3) + 4);
    g_x2[(size_t)d * 64 + lane]      = acc0 / d0;
    g_x2[(size_t)d * 64 + 32 + lane] = acc1 / d1;
}

// ---------------- ELU (+b1) ----------------
__global__ void __launch_bounds__(256) k_elu(const float* __restrict__ b1) {
    int i = blockIdx.x * blockDim.x + threadIdx.x;
    if (i >= N_NODES * 64) return;
    float v = g_x2[i] + b1[i & 63];
    g_x2[i] = v > 0.f ? v : expm1f(v);
}

// ---------------- GEMM2: h2 = x2[N,64] @ W2[64,32] ----------------
__global__ void __launch_bounds__(256) k_gemm2(const float* __restrict__ W) {
    __shared__ __align__(16) float sW[64 * 32];
    __shared__ __align__(16) float sx[32 * 64];
    int t = threadIdx.x;
    const float4* W4 = (const float4*)W;
    float4* sW4 = (float4*)sW;
#pragma unroll
    for (int i = 0; i < 2; i++) sW4[t + i * 256] = W4[t + i * 256];
    const float4* x4 = (const float4*)(g_x2 + (size_t)blockIdx.x * 32 * 64);
    float4* sx4 = (float4*)sx;
#pragma unroll
    for (int i = 0; i < 2; i++) sx4[t + i * 256] = x4[t + i * 256];
    __syncthreads();
    int ln = t >> 3, g = t & 7;
    float4 acc = make_float4(0.f, 0.f, 0.f, 0.f);
    const float* xr = sx + ln * 64;
#pragma unroll 8
    for (int k = 0; k < 64; k++) {
        float xv = xr[k];
        float4 w = *(const float4*)&sW[k * 32 + g * 4];
        acc.x += xv * w.x; acc.y += xv * w.y; acc.z += xv * w.z; acc.w += xv * w.w;
    }
    *(float4*)&g_h2[(size_t)(blockIdx.x * 32 + ln) * 32 + g * 4] = acc;
}

// ---------------- e_src/e_dst layer 2 ----------------
__global__ void __launch_bounds__(256) k_e2(const float* __restrict__ as,
                                            const float* __restrict__ ad) {
    int i = blockIdx.x * blockDim.x + threadIdx.x;
    if (i >= N_NODES) return;
    float s = 0.f, d = 0.f;
#pragma unroll
    for (int j = 0; j < 8; j++) {
        float4 v = *(const float4*)&g_h2[(size_t)i * 32 + j * 4];
        float4 a = *(const float4*)&as[j * 4];
        float4 b = *(const float4*)&ad[j * 4];
        s += v.x * a.x + v.y * a.y + v.z * a.z + v.w * a.w;
        d += v.x * b.x + v.y * b.y + v.z * b.z + v.w * b.w;
    }
    g_es2[i] = s;
    g_ed2[i] = d;
}

// ---- layer-2 FUSED softmax+aggregation: one edge pass --------------------
__global__ void __launch_bounds__(256) k_agg2f() {
    int d = (blockIdx.x * blockDim.x + threadIdx.x) >> 5;
    int lane = threadIdx.x & 31;
    if (d >= N_NODES) return;
    int beg = g_row[d], end = g_row[d + 1];
    float edd = g_ed2[d];
    float den = 0.f, acc = 0.f;
#pragma unroll 2
    for (int e = beg; e < end; e++) {
        int s = g_ssrc[e];
        float al = 0.f;
        if (lane == 0) {
            al = fexp(lrelu(g_es2[s] + edd));
            den += al;
        }
        al = __shfl_sync(0xffffffffu, al, 0);
        acc += al * g_h2[(size_t)s * 32 + lane];
    }
    den = __shfl_sync(0xffffffffu, den, 0);
    g_out2[(size_t)d * 32 + lane] = acc / den;
}

// ---------------- pooling (double accumulation) ----------------
__global__ void __launch_bounds__(256) k_pool() {
    __shared__ float sred[256];
    int c = threadIdx.x & 31;
    int grp = threadIdx.x >> 5;
    float acc = 0.f;
    for (int row = blockIdx.x * 8 + grp; row < N_NODES; row += gridDim.x * 8)
        acc += g_out2[(size_t)row * 32 + c];
    sred[threadIdx.x] = acc;
    __syncthreads();
    if (threadIdx.x < 32) {
        float s2 = 0.f;
#pragma unroll
        for (int g = 0; g < 8; g++) s2 += sred[g * 32 + threadIdx.x];
        atomicAdd(&g_pool[threadIdx.x], (double)s2);
    }
}

__global__ void k_final(const float* __restrict__ Wr, const float* __restrict__ br,
                        const float* __restrict__ b2, float* __restrict__ out) {
    if (threadIdx.x == 0) {
        double s = 0.0;
#pragma unroll
        for (int c = 0; c < 32; c++)
            s += (g_pool[c] + (double)N_NODES * (double)b2[c]) * (double)Wr[c];
        out[0] = (float)(s + (double)br[0]);
    }
}

// ---------------- launch ----------------
extern "C" void kernel_launch(void* const* d_in, const int* in_sizes, int n_in,
                              void* d_out, int out_size) {
    const float* x   = (const float*)d_in[0];
    const void*  ei  = d_in[1];
    const float* W1  = (const float*)d_in[2];
    const float* as1 = (const float*)d_in[3];
    const float* ad1 = (const float*)d_in[4];
    const float* b1  = (const float*)d_in[5];
    const float* W2  = (const float*)d_in[6];
    const float* as2 = (const float*)d_in[7];
    const float* ad2 = (const float*)d_in[8];
    const float* b2  = (const float*)d_in[9];
    const float* Wr  = (const float*)d_in[10];
    const float* br  = (const float*)d_in[11];
    float* out = (float*)d_out;

    int E = in_sizes[1] / 2;           // 3,200,000
    int Etot = E + N_NODES;            // +self loops
    int WPD = (N_NODES + 7) / 8;       // warp-per-dst grid (8 warps/block)

    k_detect<<<1, 256>>>((const int*)ei);
    k_init<<<(N_NODES + 255) / 256, 256>>>();
    k_edges<<<(Etot + 255) / 256, 256>>>(ei, E, Etot);
    k_scan1<<<NSCAN, SCAN_B>>>();
    k_scan2<<<1, 128>>>();
    k_scan3<<<(N_NODES + 255) / 256, 256>>>(Etot);
    k_scatter<<<(Etot + 255) / 256, 256>>>(Etot);
    k_gemm1<<<N_NODES / 16, 256>>>(x, W1);
    k_e1<<<(N_NODES * 8 + 255) / 256, 256>>>(as1, ad1);
    k_agg1f<<<WPD, 256>>>();
    k_elu<<<(N_NODES * 64 + 255) / 256, 256>>>(b1);
    k_gemm2<<<N_NODES / 32, 256>>>(W2);
    k_e2<<<(N_NODES + 255) / 256, 256>>>(as2, ad2);
    k_agg2f<<<WPD, 256>>>();
    k_pool<<<512, 256>>>();
    k_final<<<1, 32>>>(Wr, br, b2, out);
}

// round 13
// speedup vs baseline: 1.3394x; 1.3394x over previous
#include <cuda_runtime.h>
#include <math_constants.h>

#define N_NODES 100000
#define MAX_ETOT 3300000   // 3.2M edges + 100k self-loops
#define SCAN_B 1024
#define NSCAN ((N_NODES + SCAN_B - 1) / SCAN_B)   // 98

// ---------------- scratch (device globals; no allocation allowed) ----------
__device__ int      g_is64;
__device__ int      g_src[MAX_ETOT];
__device__ int      g_dst[MAX_ETOT];
__device__ int      g_cnt[N_NODES];
__device__ int      g_row[N_NODES + 1];
__device__ int      g_woff[N_NODES];
__device__ int      g_bsum[NSCAN];
__device__ int      g_ssrc[MAX_ETOT];
__device__ __align__(16) float g_e1 [MAX_ETOT * 8]; // per-edge per-head exp(e); reused layer 2
__device__ __align__(16) float g_h1 [N_NODES * 64];
__device__ __align__(16) float g_es1[N_NODES * 8];
__device__ __align__(16) float g_ed1[N_NODES * 8];
__device__ __align__(16) float g_d1 [N_NODES * 8];  // 1/denom per (dst, head)
__device__ __align__(16) float g_x2 [N_NODES * 64];
__device__ __align__(16) float g_h2 [N_NODES * 32];
__device__ float    g_es2[N_NODES];
__device__ float    g_ed2[N_NODES];
__device__ float    g_d2 [N_NODES];
__device__ float    g_out2[N_NODES * 32];
__device__ double   g_pool[32];

// ---------------- helpers ----------------
__device__ __forceinline__ float lrelu(float v) { return v > 0.f ? v : 0.2f * v; }
__device__ __forceinline__ int clampN(int v) {
    return v < 0 ? 0 : (v >= N_NODES ? N_NODES - 1 : v);
}
// fast exp on FMA/ALU pipes (no MUFU). rel err ~2.4e-6 over |x| < 88.
__device__ __forceinline__ float fexp(float x) {
    x = fmaxf(fminf(x, 80.f), -80.f);
    float y = x * 1.4426950408889634f;     // log2(e)
    float fl = rintf(y);
    float f = y - fl;                      // f in [-0.5, 0.5]
    int   i = (int)fl;
    float p =            1.3333558146428443e-3f;
    p = fmaf(p, f, 9.618129107628477e-3f);
    p = fmaf(p, f, 5.550410866482158e-2f);
    p = fmaf(p, f, 2.402265069591007e-1f);
    p = fmaf(p, f, 6.931471805599453e-1f);
    p = fmaf(p, f, 1.0f);
    return __int_as_float((i + 127) << 23) * p;
}

// ---------------- dtype sniff ----------------
__global__ void k_detect(const int* __restrict__ e) {
    __shared__ int any;
    if (threadIdx.x == 0) any = 0;
    __syncthreads();
    int acc = 0;
    for (int i = 2 * threadIdx.x + 1; i < 4096; i += 2 * blockDim.x) acc |= e[i];
    if (acc) atomicOr(&any, 1);
    __syncthreads();
    if (threadIdx.x == 0) g_is64 = (any == 0) ? 1 : 0;
}

// ---------------- init (before k_edges: histogram fused there) ------------
__global__ void __launch_bounds__(256) k_init() {
    int j = blockIdx.x * blockDim.x + threadIdx.x;
    if (j < N_NODES) g_cnt[j] = 0;
    if (j < 32)      g_pool[j] = 0.0;
}

// -------- prep: edges -> int32, self-loops appended, degree histogram -----
__global__ void __launch_bounds__(256) k_edges(const void* __restrict__ eraw,
                                               int E, int Etot) {
    int i = blockIdx.x * blockDim.x + threadIdx.x;
    if (i >= Etot) return;
    int s, d;
    if (i >= E) { s = i - E; d = s; }
    else if (g_is64) {
        const long long* e64 = (const long long*)eraw;
        s = clampN((int)e64[i]);
        d = clampN((int)e64[E + i]);
    } else {
        const int* e32 = (const int*)eraw;
        s = clampN(e32[i]);
        d = clampN(e32[E + i]);
    }
    g_src[i] = s;
    g_dst[i] = d;
    atomicAdd(&g_cnt[d], 1);
}

// ---------------- CSR build ----------------
__global__ void __launch_bounds__(SCAN_B) k_scan1() {
    __shared__ int sh[SCAN_B];
    int t = threadIdx.x;
    int i = blockIdx.x * SCAN_B + t;
    int v = (i < N_NODES) ? g_cnt[i] : 0;
    sh[t] = v;
    __syncthreads();
    for (int o = 1; o < SCAN_B; o <<= 1) {
        int x = (t >= o) ? sh[t - o] : 0;
        __syncthreads();
        sh[t] += x;
        __syncthreads();
    }
    if (i < N_NODES) g_row[i] = sh[t] - v;
    if (t == SCAN_B - 1) g_bsum[blockIdx.x] = sh[t];
}

__global__ void __launch_bounds__(128) k_scan2() {
    __shared__ int sh[128];
    int t = threadIdx.x;
    int v = (t < NSCAN) ? g_bsum[t] : 0;
    sh[t] = v;
    __syncthreads();
    for (int o = 1; o < 128; o <<= 1) {
        int x = (t >= o) ? sh[t - o] : 0;
        __syncthreads();
        sh[t] += x;
        __syncthreads();
    }
    if (t < NSCAN) g_bsum[t] = sh[t] - v;
}

__global__ void __launch_bounds__(256) k_scan3(int Etot) {
    int i = blockIdx.x * blockDim.x + threadIdx.x;
    if (i < N_NODES) {
        int r = g_row[i] + g_bsum[i / SCAN_B];
        g_row[i] = r;
        g_woff[i] = r;
    }
    if (i == 0) g_row[N_NODES] = Etot;
}

__global__ void __launch_bounds__(256) k_scatter(int Etot) {
    int i = blockIdx.x * blockDim.x + threadIdx.x;
    if (i >= Etot) return;
    int pos = atomicAdd(&g_woff[g_dst[i]], 1);
    g_ssrc[pos] = g_src[i];
}

// ------- GEMM1 + fused e1: h1 = x @ W1; es1/ed1 = <h1, a_src/a_dst> -------
// 128 nodes/block, 256 threads; thread = 4 nodes x 8 cols (cols = one head)
__global__ void __launch_bounds__(256) k_gemm1(const float* __restrict__ x,
                                               const float* __restrict__ W,
                                               const float* __restrict__ as,
                                               const float* __restrict__ ad) {
    __shared__ __align__(16) float sW[128 * 64];
    __shared__ __align__(16) float sx[128 * 68];    // pad 68 kills bank conflicts
    int t = threadIdx.x;
    const float4* W4 = (const float4*)W;
    float4* sW4 = (float4*)sW;
#pragma unroll
    for (int i = 0; i < 8; i++) sW4[t + i * 256] = W4[t + i * 256];
    int ty = t >> 3, tx = t & 7;
    int n0 = blockIdx.x * 128 + ty * 4;
    float acc[4][8];
#pragma unroll
    for (int i = 0; i < 4; i++)
#pragma unroll
        for (int j = 0; j < 8; j++) acc[i][j] = 0.f;

#pragma unroll
    for (int kc = 0; kc < 2; kc++) {
        __syncthreads();
#pragma unroll
        for (int i = 0; i < 8; i++) {
            int q = t + i * 256;             // 0..2047
            int row = q >> 4, j4 = q & 15;
            int gr = blockIdx.x * 128 + row;
            float4 v = make_float4(0.f, 0.f, 0.f, 0.f);
            if (gr < N_NODES) v = *(const float4*)&x[(size_t)gr * 128 + kc * 64 + j4 * 4];
            *(float4*)&sx[row * 68 + j4 * 4] = v;
        }
        __syncthreads();
#pragma unroll 8
        for (int k = 0; k < 64; k++) {
            float4 wa = *(const float4*)&sW[(kc * 64 + k) * 64 + tx * 8];
            float4 wb = *(const float4*)&sW[(kc * 64 + k) * 64 + tx * 8 + 4];
#pragma unroll
            for (int i = 0; i < 4; i++) {
                float xv = sx[(ty * 4 + i) * 68 + k];
                acc[i][0] += xv * wa.x; acc[i][1] += xv * wa.y;
                acc[i][2] += xv * wa.z; acc[i][3] += xv * wa.w;
                acc[i][4] += xv * wb.x; acc[i][5] += xv * wb.y;
                acc[i][6] += xv * wb.z; acc[i][7] += xv * wb.w;
            }
        }
    }
    float a_s[8], a_d[8];
#pragma unroll
    for (int j = 0; j < 8; j++) { a_s[j] = as[tx * 8 + j]; a_d[j] = ad[tx * 8 + j]; }
#pragma unroll
    for (int i = 0; i < 4; i++) {
        int n = n0 + i;
        if (n < N_NODES) {
            *(float4*)&g_h1[(size_t)n * 64 + tx * 8] =
                make_float4(acc[i][0], acc[i][1], acc[i][2], acc[i][3]);
            *(float4*)&g_h1[(size_t)n * 64 + tx * 8 + 4] =
                make_float4(acc[i][4], acc[i][5], acc[i][6], acc[i][7]);
            float es = 0.f, ed = 0.f;
#pragma unroll
            for (int j = 0; j < 8; j++) { es += acc[i][j] * a_s[j]; ed += acc[i][j] * a_d[j]; }
            g_es1[n * 8 + tx] = es;
            g_ed1[n * 8 + tx] = ed;
        }
    }
}

// ------ layer-1 softmax: single pass, max-free (logits are O(1)) ---------
__global__ void __launch_bounds__(256) k_soft1() {
    int d = (blockIdx.x * blockDim.x + threadIdx.x) >> 5;
    int lane = threadIdx.x & 31;
    if (d >= N_NODES) return;
    int beg = g_row[d], end = g_row[d + 1];
    float4 eda = *(const float4*)&g_ed1[d * 8];
    float4 edb = *(const float4*)&g_ed1[d * 8 + 4];
    float ed[8] = {eda.x, eda.y, eda.z, eda.w, edb.x, edb.y, edb.z, edb.w};
    float sum[8] = {0.f, 0.f, 0.f, 0.f, 0.f, 0.f, 0.f, 0.f};
    for (int e = beg + lane; e < end; e += 32) {
        int s = g_ssrc[e];
        float4 sa = *(const float4*)&g_es1[s * 8];
        float4 sb = *(const float4*)&g_es1[s * 8 + 4];
        float ex[8] = {fexp(lrelu(sa.x + ed[0])), fexp(lrelu(sa.y + ed[1])),
                       fexp(lrelu(sa.z + ed[2])), fexp(lrelu(sa.w + ed[3])),
                       fexp(lrelu(sb.x + ed[4])), fexp(lrelu(sb.y + ed[5])),
                       fexp(lrelu(sb.z + ed[6])), fexp(lrelu(sb.w + ed[7]))};
        *(float4*)&g_e1[(size_t)e * 8]     = make_float4(ex[0], ex[1], ex[2], ex[3]);
        *(float4*)&g_e1[(size_t)e * 8 + 4] = make_float4(ex[4], ex[5], ex[6], ex[7]);
#pragma unroll
        for (int h = 0; h < 8; h++) sum[h] += ex[h];
    }
#pragma unroll
    for (int h = 0; h < 8; h++)
#pragma unroll
        for (int o = 16; o > 0; o >>= 1)
            sum[h] += __shfl_xor_sync(0xffffffffu, sum[h], o);
    if (lane == 0) {
        *(float4*)&g_d1[d * 8] =
            make_float4(1.f / sum[0], 1.f / sum[1], 1.f / sum[2], 1.f / sum[3]);
        *(float4*)&g_d1[d * 8 + 4] =
            make_float4(1.f / sum[4], 1.f / sum[5], 1.f / sum[6], 1.f / sum[7]);
    }
}

// ---------------- layer-1 aggregation: warp per dst, no atomics ----------
__global__ void __launch_bounds__(256) k_agg1c() {
    int d = (blockIdx.x * blockDim.x + threadIdx.x) >> 5;
    int lane = threadIdx.x & 31;
    if (d >= N_NODES) return;
    int beg = g_row[d], end = g_row[d + 1];
    float rd0 = g_d1[d * 8 + (lane >> 3)];
    float rd1 = g_d1[d * 8 + 4 + (lane >> 3)];
    float acc0 = 0.f, acc1 = 0.f;
#pragma unroll 2
    for (int e = beg; e < end; e++) {
        int s = g_ssrc[e];
        float a0 = g_e1[(size_t)e * 8 + (lane >> 3)] * rd0;
        float a1 = g_e1[(size_t)e * 8 + 4 + (lane >> 3)] * rd1;
        acc0 += a0 * g_h1[(size_t)s * 64 + lane];
        acc1 += a1 * g_h1[(size_t)s * 64 + 32 + lane];
    }
    g_x2[(size_t)d * 64 + lane] = acc0;
    g_x2[(size_t)d * 64 + 32 + lane] = acc1;
}

// ---------------- ELU (+b1) ----------------
__global__ void __launch_bounds__(256) k_elu(const float* __restrict__ b1) {
    int i = blockIdx.x * blockDim.x + threadIdx.x;
    if (i >= N_NODES * 64) return;
    float v = g_x2[i] + b1[i & 63];
    g_x2[i] = v > 0.f ? v : expm1f(v);
}

// ---------------- GEMM2: h2 = x2[N,64] @ W2[64,32] ----------------
__global__ void __launch_bounds__(256) k_gemm2(const float* __restrict__ W) {
    __shared__ __align__(16) float sW[64 * 32];
    __shared__ __align__(16) float sx[32 * 64];
    int t = threadIdx.x;
    const float4* W4 = (const float4*)W;
    float4* sW4 = (float4*)sW;
#pragma unroll
    for (int i = 0; i < 2; i++) sW4[t + i * 256] = W4[t + i * 256];
    const float4* x4 = (const float4*)(g_x2 + (size_t)blockIdx.x * 32 * 64);
    float4* sx4 = (float4*)sx;
#pragma unroll
    for (int i = 0; i < 2; i++) sx4[t + i * 256] = x4[t + i * 256];
    __syncthreads();
    int ln = t >> 3, g = t & 7;
    float4 acc = make_float4(0.f, 0.f, 0.f, 0.f);
    const float* xr = sx + ln * 64;
#pragma unroll 8
    for (int k = 0; k < 64; k++) {
        float xv = xr[k];
        float4 w = *(const float4*)&sW[k * 32 + g * 4];
        acc.x += xv * w.x; acc.y += xv * w.y; acc.z += xv * w.z; acc.w += xv * w.w;
    }
    *(float4*)&g_h2[(size_t)(blockIdx.x * 32 + ln) * 32 + g * 4] = acc;
}

// ---------------- e_src/e_dst layer 2 ----------------
__global__ void __launch_bounds__(256) k_e2(const float* __restrict__ as,
                                            const float* __restrict__ ad) {
    int i = blockIdx.x * blockDim.x + threadIdx.x;
    if (i >= N_NODES) return;
    float s = 0.f, d = 0.f;
#pragma unroll
    for (int j = 0; j < 8; j++) {
        float4 v = *(const float4*)&g_h2[(size_t)i * 32 + j * 4];
        float4 a = *(const float4*)&as[j * 4];
        float4 b = *(const float4*)&ad[j * 4];
        s += v.x * a.x + v.y * a.y + v.z * a.z + v.w * a.w;
        d += v.x * b.x + v.y * b.y + v.z * b.z + v.w * b.w;
    }
    g_es2[i] = s;
    g_ed2[i] = d;
}

// ------ layer-2 softmax: single pass, max-free ---------------------------
__global__ void __launch_bounds__(256) k_soft2() {
    int d = (blockIdx.x * blockDim.x + threadIdx.x) >> 5;
    int lane = threadIdx.x & 31;
    if (d >= N_NODES) return;
    int beg = g_row[d], end = g_row[d + 1];
    float edd = g_ed2[d];
    float sum = 0.f;
    for (int e = beg + lane; e < end; e += 32) {
        float ex = fexp(lrelu(g_es2[g_ssrc[e]] + edd));
        g_e1[e] = ex;
        sum += ex;
    }
#pragma unroll
    for (int o = 16; o > 0; o >>= 1)
        sum += __shfl_xor_sync(0xffffffffu, sum, o);
    if (lane == 0) g_d2[d] = 1.f / sum;
}

// ---------------- layer-2 aggregation: warp per dst ----------------
__global__ void __launch_bounds__(256) k_agg2c() {
    int d = (blockIdx.x * blockDim.x + threadIdx.x) >> 5;
    int lane = threadIdx.x & 31;
    if (d >= N_NODES) return;
    int beg = g_row[d], end = g_row[d + 1];
    float rd = g_d2[d];
    float acc = 0.f;
#pragma unroll 2
    for (int e = beg; e < end; e++) {
        int s = g_ssrc[e];
        float a = g_e1[e] * rd;
        acc += a * g_h2[(size_t)s * 32 + lane];
    }
    g_out2[(size_t)d * 32 + lane] = acc;
}

// ---------------- pooling (double accumulation) ----------------
__global__ void __launch_bounds__(256) k_pool() {
    __shared__ float sred[256];
    int c = threadIdx.x & 31;
    int grp = threadIdx.x >> 5;
    float acc = 0.f;
    for (int row = blockIdx.x * 8 + grp; row < N_NODES; row += gridDim.x * 8)
        acc += g_out2[(size_t)row * 32 + c];
    sred[threadIdx.x] = acc;
    __syncthreads();
    if (threadIdx.x < 32) {
        float s2 = 0.f;
#pragma unroll
        for (int g = 0; g < 8; g++) s2 += sred[g * 32 + threadIdx.x];
        atomicAdd(&g_pool[threadIdx.x], (double)s2);
    }
}

__global__ void k_final(const float* __restrict__ Wr, const float* __restrict__ br,
                        const float* __restrict__ b2, float* __restrict__ out) {
    if (threadIdx.x == 0) {
        double s = 0.0;
#pragma unroll
        for (int c = 0; c < 32; c++)
            s += (g_pool[c] + (double)N_NODES * (double)b2[c]) * (double)Wr[c];
        out[0] = (float)(s + (double)br[0]);
    }
}

// ---------------- launch ----------------
extern "C" void kernel_launch(void* const* d_in, const int* in_sizes, int n_in,
                              void* d_out, int out_size) {
    const float* x   = (const float*)d_in[0];
    const void*  ei  = d_in[1];
    const float* W1  = (const float*)d_in[2];
    const float* as1 = (const float*)d_in[3];
    const float* ad1 = (const float*)d_in[4];
    const float* b1  = (const float*)d_in[5];
    const float* W2  = (const float*)d_in[6];
    const float* as2 = (const float*)d_in[7];
    const float* ad2 = (const float*)d_in[8];
    const float* b2  = (const float*)d_in[9];
    const float* Wr  = (const float*)d_in[10];
    const float* br  = (const float*)d_in[11];
    float* out = (float*)d_out;

    int E = in_sizes[1] / 2;           // 3,200,000
    int Etot = E + N_NODES;            // +self loops
    int WPD = (N_NODES + 7) / 8;       // warp-per-dst grid (8 warps/block)

    k_detect<<<1, 256>>>((const int*)ei);
    k_init<<<(N_NODES + 255) / 256, 256>>>();
    k_edges<<<(Etot + 255) / 256, 256>>>(ei, E, Etot);
    k_scan1<<<NSCAN, SCAN_B>>>();
    k_scan2<<<1, 128>>>();
    k_scan3<<<(N_NODES + 255) / 256, 256>>>(Etot);
    k_scatter<<<(Etot + 255) / 256, 256>>>(Etot);
    k_gemm1<<<(N_NODES + 127) / 128, 256>>>(x, W1, as1, ad1);
    k_soft1<<<WPD, 256>>>();
    k_agg1c<<<WPD, 256>>>();
    k_elu<<<(N_NODES * 64 + 255) / 256, 256>>>(b1);
    k_gemm2<<<N_NODES / 32, 256>>>(W2);
    k_e2<<<(N_NODES + 255) / 256, 256>>>(as2, ad2);
    k_soft2<<<WPD, 256>>>();
    k_agg2c<<<WPD, 256>>>();
    k_pool<<<512, 256>>>();
    k_final<<<1, 32>>>(Wr, br, b2, out);
}

// round 15
// speedup vs baseline: 1.5633x; 1.1672x over previous
#include <cuda_runtime.h>
#include <cuda_fp16.h>
#include <math_constants.h>

#define N_NODES 100000
#define MAX_ETOT 3300000   // 3.2M edges + 100k self-loops
#define SCAN_B 1024
#define NSCAN ((N_NODES + SCAN_B - 1) / SCAN_B)   // 98

// ---------------- scratch (device globals; no allocation allowed) ----------
__device__ int      g_is64;
__device__ int      g_src[MAX_ETOT];
__device__ int      g_dst[MAX_ETOT];
__device__ int      g_cnt[N_NODES];
__device__ int      g_row[N_NODES + 1];
__device__ int      g_woff[N_NODES];
__device__ int      g_bsum[NSCAN];
__device__ int      g_ssrc[MAX_ETOT];
__device__ __align__(16) __half2 g_e1h[MAX_ETOT * 4];  // per-edge 8 heads exp(e), half
__device__ __align__(16) __half2 g_h1h[N_NODES * 32];  // h1 as half2 (64 cols)
__device__ __align__(16) float   g_es1[N_NODES * 8];
__device__ __align__(16) float   g_ed1[N_NODES * 8];
__device__ __align__(16) float   g_d1 [N_NODES * 8];   // 1/denom per (dst, head)
__device__ __align__(16) float   g_x2 [N_NODES * 64];  // ELU'd layer-1 out
__device__ __align__(16) __half  g_h2h[N_NODES * 32];  // h2 as half
__device__ float    g_a2 [MAX_ETOT];                   // layer-2 exp per edge
__device__ float    g_es2[N_NODES];
__device__ float    g_ed2[N_NODES];
__device__ float    g_d2 [N_NODES];
__device__ float    g_out2[N_NODES * 32];
__device__ double   g_pool[32];

// ---------------- helpers ----------------
__device__ __forceinline__ float lrelu(float v) { return v > 0.f ? v : 0.2f * v; }
__device__ __forceinline__ int clampN(int v) {
    return v < 0 ? 0 : (v >= N_NODES ? N_NODES - 1 : v);
}
// fast exp on FMA/ALU pipes (no MUFU). rel err ~2.4e-6 over |x| < 88.
__device__ __forceinline__ float fexp(float x) {
    x = fmaxf(fminf(x, 80.f), -80.f);
    float y = x * 1.4426950408889634f;     // log2(e)
    float fl = rintf(y);
    float f = y - fl;                      // f in [-0.5, 0.5]
    int   i = (int)fl;
    float p =            1.3333558146428443e-3f;
    p = fmaf(p, f, 9.618129107628477e-3f);
    p = fmaf(p, f, 5.550410866482158e-2f);
    p = fmaf(p, f, 2.402265069591007e-1f);
    p = fmaf(p, f, 6.931471805599453e-1f);
    p = fmaf(p, f, 1.0f);
    return __int_as_float((i + 127) << 23) * p;
}

// ---------------- dtype sniff ----------------
__global__ void k_detect(const int* __restrict__ e) {
    __shared__ int any;
    if (threadIdx.x == 0) any = 0;
    __syncthreads();
    int acc = 0;
    for (int i = 2 * threadIdx.x + 1; i < 4096; i += 2 * blockDim.x) acc |= e[i];
    if (acc) atomicOr(&any, 1);
    __syncthreads();
    if (threadIdx.x == 0) g_is64 = (any == 0) ? 1 : 0;
}

// ---------------- init ----------------
__global__ void __launch_bounds__(256) k_init() {
    int j = blockIdx.x * blockDim.x + threadIdx.x;
    if (j < N_NODES) g_cnt[j] = 0;
    if (j < 32)      g_pool[j] = 0.0;
}

// -------- prep: edges -> int32, self-loops appended, degree histogram -----
__global__ void __launch_bounds__(256) k_edges(const void* __restrict__ eraw,
                                               int E, int Etot) {
    int i = blockIdx.x * blockDim.x + threadIdx.x;
    if (i >= Etot) return;
    int s, d;
    if (i >= E) { s = i - E; d = s; }
    else if (g_is64) {
        const long long* e64 = (const long long*)eraw;
        s = clampN((int)e64[i]);
        d = clampN((int)e64[E + i]);
    } else {
        const int* e32 = (const int*)eraw;
        s = clampN(e32[i]);
        d = clampN(e32[E + i]);
    }
    g_src[i] = s;
    g_dst[i] = d;
    atomicAdd(&g_cnt[d], 1);
}

// ---------------- CSR build ----------------
__global__ void __launch_bounds__(SCAN_B) k_scan1() {
    __shared__ int sh[SCAN_B];
    int t = threadIdx.x;
    int i = blockIdx.x * SCAN_B + t;
    int v = (i < N_NODES) ? g_cnt[i] : 0;
    sh[t] = v;
    __syncthreads();
    for (int o = 1; o < SCAN_B; o <<= 1) {
        int x = (t >= o) ? sh[t - o] : 0;
        __syncthreads();
        sh[t] += x;
        __syncthreads();
    }
    if (i < N_NODES) g_row[i] = sh[t] - v;
    if (t == SCAN_B - 1) g_bsum[blockIdx.x] = sh[t];
}

__global__ void __launch_bounds__(128) k_scan2() {
    __shared__ int sh[128];
    int t = threadIdx.x;
    int v = (t < NSCAN) ? g_bsum[t] : 0;
    sh[t] = v;
    __syncthreads();
    for (int o = 1; o < 128; o <<= 1) {
        int x = (t >= o) ? sh[t - o] : 0;
        __syncthreads();
        sh[t] += x;
        __syncthreads();
    }
    if (t < NSCAN) g_bsum[t] = sh[t] - v;
}

__global__ void __launch_bounds__(256) k_scan3(int Etot) {
    int i = blockIdx.x * blockDim.x + threadIdx.x;
    if (i < N_NODES) {
        int r = g_row[i] + g_bsum[i / SCAN_B];
        g_row[i] = r;
        g_woff[i] = r;
    }
    if (i == 0) g_row[N_NODES] = Etot;
}

__global__ void __launch_bounds__(256) k_scatter(int Etot) {
    int i = blockIdx.x * blockDim.x + threadIdx.x;
    if (i >= Etot) return;
    int pos = atomicAdd(&g_woff[g_dst[i]], 1);
    g_ssrc[pos] = g_src[i];
}

// ------- GEMM1 + fused e1: h1(half) = x @ W1; es1/ed1 from fp32 accs ------
__global__ void __launch_bounds__(256) k_gemm1(const float* __restrict__ x,
                                               const float* __restrict__ W,
                                               const float* __restrict__ as,
                                               const float* __restrict__ ad) {
    __shared__ __align__(16) float sW[128 * 64];
    __shared__ __align__(16) float sx[128 * 68];    // pad 68 kills bank conflicts
    int t = threadIdx.x;
    const float4* W4 = (const float4*)W;
    float4* sW4 = (float4*)sW;
#pragma unroll
    for (int i = 0; i < 8; i++) sW4[t + i * 256] = W4[t + i * 256];
    int ty = t >> 3, tx = t & 7;
    int n0 = blockIdx.x * 128 + ty * 4;
    float acc[4][8];
#pragma unroll
    for (int i = 0; i < 4; i++)
#pragma unroll
        for (int j = 0; j < 8; j++) acc[i][j] = 0.f;

#pragma unroll
    for (int kc = 0; kc < 2; kc++) {
        __syncthreads();
#pragma unroll
        for (int i = 0; i < 8; i++) {
            int q = t + i * 256;
            int row = q >> 4, j4 = q & 15;
            int gr = blockIdx.x * 128 + row;
            float4 v = make_float4(0.f, 0.f, 0.f, 0.f);
            if (gr < N_NODES) v = *(const float4*)&x[(size_t)gr * 128 + kc * 64 + j4 * 4];
            *(float4*)&sx[row * 68 + j4 * 4] = v;
        }
        __syncthreads();
#pragma unroll 8
        for (int k = 0; k < 64; k++) {
            float4 wa = *(const float4*)&sW[(kc * 64 + k) * 64 + tx * 8];
            float4 wb = *(const float4*)&sW[(kc * 64 + k) * 64 + tx * 8 + 4];
#pragma unroll
            for (int i = 0; i < 4; i++) {
                float xv = sx[(ty * 4 + i) * 68 + k];
                acc[i][0] += xv * wa.x; acc[i][1] += xv * wa.y;
                acc[i][2] += xv * wa.z; acc[i][3] += xv * wa.w;
                acc[i][4] += xv * wb.x; acc[i][5] += xv * wb.y;
                acc[i][6] += xv * wb.z; acc[i][7] += xv * wb.w;
            }
        }
    }
    float a_s[8], a_d[8];
#pragma unroll
    for (int j = 0; j < 8; j++) { a_s[j] = as[tx * 8 + j]; a_d[j] = ad[tx * 8 + j]; }
#pragma unroll
    for (int i = 0; i < 4; i++) {
        int n = n0 + i;
        if (n < N_NODES) {
            __half2 hp[4];
#pragma unroll
            for (int j = 0; j < 4; j++)
                hp[j] = __floats2half2_rn(acc[i][2 * j], acc[i][2 * j + 1]);
            *(uint4*)&g_h1h[(size_t)n * 32 + tx * 4] = *(uint4*)hp;
            float es = 0.f, ed = 0.f;
#pragma unroll
            for (int j = 0; j < 8; j++) { es += acc[i][j] * a_s[j]; ed += acc[i][j] * a_d[j]; }
            g_es1[n * 8 + tx] = es;
            g_ed1[n * 8 + tx] = ed;
        }
    }
}

// ------ layer-1 softmax: single pass, max-free; exps stored as half ------
__global__ void __launch_bounds__(256) k_soft1() {
    int d = (blockIdx.x * blockDim.x + threadIdx.x) >> 5;
    int lane = threadIdx.x & 31;
    if (d >= N_NODES) return;
    int beg = g_row[d], end = g_row[d + 1];
    float4 eda = *(const float4*)&g_ed1[d * 8];
    float4 edb = *(const float4*)&g_ed1[d * 8 + 4];
    float ed[8] = {eda.x, eda.y, eda.z, eda.w, edb.x, edb.y, edb.z, edb.w};
    float sum[8] = {0.f, 0.f, 0.f, 0.f, 0.f, 0.f, 0.f, 0.f};
    for (int e = beg + lane; e < end; e += 32) {
        int s = g_ssrc[e];
        float4 sa = *(const float4*)&g_es1[s * 8];
        float4 sb = *(const float4*)&g_es1[s * 8 + 4];
        float ex[8] = {fexp(lrelu(sa.x + ed[0])), fexp(lrelu(sa.y + ed[1])),
                       fexp(lrelu(sa.z + ed[2])), fexp(lrelu(sa.w + ed[3])),
                       fexp(lrelu(sb.x + ed[4])), fexp(lrelu(sb.y + ed[5])),
                       fexp(lrelu(sb.z + ed[6])), fexp(lrelu(sb.w + ed[7]))};
        __half2 hp[4];
#pragma unroll
        for (int j = 0; j < 4; j++) hp[j] = __floats2half2_rn(ex[2 * j], ex[2 * j + 1]);
        *(uint4*)&g_e1h[(size_t)e * 4] = *(uint4*)hp;
#pragma unroll
        for (int h = 0; h < 8; h++) sum[h] += ex[h];
    }
#pragma unroll
    for (int h = 0; h < 8; h++)
#pragma unroll
        for (int o = 16; o > 0; o >>= 1)
            sum[h] += __shfl_xor_sync(0xffffffffu, sum[h], o);
    if (lane == 0) {
        *(float4*)&g_d1[d * 8] =
            make_float4(1.f / sum[0], 1.f / sum[1], 1.f / sum[2], 1.f / sum[3]);
        *(float4*)&g_d1[d * 8 + 4] =
            make_float4(1.f / sum[4], 1.f / sum[5], 1.f / sum[6], 1.f / sum[7]);
    }
}

// ---- layer-1 aggregation + fused ELU(+b1): lane owns features 2l,2l+1 ----
__global__ void __launch_bounds__(256) k_agg1c(const float* __restrict__ b1) {
    int d = (blockIdx.x * blockDim.x + threadIdx.x) >> 5;
    int lane = threadIdx.x & 31;
    if (d >= N_NODES) return;
    int beg = g_row[d], end = g_row[d + 1];
    int h = lane >> 2;                         // head of features 2l, 2l+1
    float rd = g_d1[d * 8 + h];
    float2 bv = *(const float2*)&b1[2 * lane];
    float accx = 0.f, accy = 0.f;
#pragma unroll 4
    for (int e = beg; e < end; e++) {
        int s = g_ssrc[e];
        __half2 ap = g_e1h[(size_t)e * 4 + (h >> 1)];
        float2 af = __half22float2(ap);
        float a = (h & 1) ? af.y : af.x;
        float2 v = __half22float2(g_h1h[(size_t)s * 32 + lane]);
        accx += a * v.x;
        accy += a * v.y;
    }
    float vx = accx * rd + bv.x;
    float vy = accy * rd + bv.y;
    vx = vx > 0.f ? vx : expm1f(vx);
    vy = vy > 0.f ? vy : expm1f(vy);
    *(float2*)&g_x2[(size_t)d * 64 + 2 * lane] = make_float2(vx, vy);
}

// ------ GEMM2 + fused e2: h2(half) = x2 @ W2; es2/ed2 via width-8 shfl ----
__global__ void __launch_bounds__(256) k_gemm2(const float* __restrict__ W,
                                               const float* __restrict__ as,
                                               const float* __restrict__ ad) {
    __shared__ __align__(16) float sW[64 * 32];
    __shared__ __align__(16) float sx[32 * 64];
    int t = threadIdx.x;
    const float4* W4 = (const float4*)W;
    float4* sW4 = (float4*)sW;
#pragma unroll
    for (int i = 0; i < 2; i++) sW4[t + i * 256] = W4[t + i * 256];
    const float4* x4 = (const float4*)(g_x2 + (size_t)blockIdx.x * 32 * 64);
    float4* sx4 = (float4*)sx;
#pragma unroll
    for (int i = 0; i < 2; i++) sx4[t + i * 256] = x4[t + i * 256];
    __syncthreads();
    int ln = t >> 3, g = t & 7;
    float4 acc = make_float4(0.f, 0.f, 0.f, 0.f);
    const float* xr = sx + ln * 64;
#pragma unroll 8
    for (int k = 0; k < 64; k++) {
        float xv = xr[k];
        float4 w = *(const float4*)&sW[k * 32 + g * 4];
        acc.x += xv * w.x; acc.y += xv * w.y; acc.z += xv * w.z; acc.w += xv * w.w;
    }
    int node = blockIdx.x * 32 + ln;
    // half h2 store
    __half2 hp0 = __floats2half2_rn(acc.x, acc.y);
    __half2 hp1 = __floats2half2_rn(acc.z, acc.w);
    __half2* h2p = (__half2*)g_h2h;
    h2p[(size_t)node * 16 + g * 2]     = hp0;
    h2p[(size_t)node * 16 + g * 2 + 1] = hp1;
    // fused e2: dot over this thread's 4 cols, reduce across the 8 col-groups
    float4 av = *(const float4*)&as[g * 4];
    float4 bvv = *(const float4*)&ad[g * 4];
    float es = acc.x * av.x + acc.y * av.y + acc.z * av.z + acc.w * av.w;
    float edv = acc.x * bvv.x + acc.y * bvv.y + acc.z * bvv.z + acc.w * bvv.w;
#pragma unroll
    for (int o = 4; o > 0; o >>= 1) {
        es  += __shfl_down_sync(0xffffffffu, es, o, 8);
        edv += __shfl_down_sync(0xffffffffu, edv, o, 8);
    }
    if (g == 0) { g_es2[node] = es; g_ed2[node] = edv; }
}

// ------ layer-2 softmax: single pass, max-free ---------------------------
__global__ void __launch_bounds__(256) k_soft2() {
    int d = (blockIdx.x * blockDim.x + threadIdx.x) >> 5;
    int lane = threadIdx.x & 31;
    if (d >= N_NODES) return;
    int beg = g_row[d], end = g_row[d + 1];
    float edd = g_ed2[d];
    float sum = 0.f;
    for (int e = beg + lane; e < end; e += 32) {
        float ex = fexp(lrelu(g_es2[g_ssrc[e]] + edd));
        g_a2[e] = ex;
        sum += ex;
    }
#pragma unroll
    for (int o = 16; o > 0; o >>= 1)
        sum += __shfl_xor_sync(0xffffffffu, sum, o);
    if (lane == 0) g_d2[d] = 1.f / sum;
}

// ---------------- layer-2 aggregation: warp per dst, half h2 --------------
__global__ void __launch_bounds__(256) k_agg2c() {
    int d = (blockIdx.x * blockDim.x + threadIdx.x) >> 5;
    int lane = threadIdx.x & 31;
    if (d >= N_NODES) return;
    int beg = g_row[d], end = g_row[d + 1];
    float rd = g_d2[d];
    float acc = 0.f;
#pragma unroll 4
    for (int e = beg; e < end; e++) {
        int s = g_ssrc[e];
        float a = g_a2[e];
        acc += a * __half2float(g_h2h[(size_t)s * 32 + lane]);
    }
    g_out2[(size_t)d * 32 + lane] = acc * rd;
}

// ---------------- pooling (double accumulation) ----------------
__global__ void __launch_bounds__(256) k_pool() {
    __shared__ float sred[256];
    int c = threadIdx.x & 31;
    int grp = threadIdx.x >> 5;
    float acc = 0.f;
    for (int row = blockIdx.x * 8 + grp; row < N_NODES; row += gridDim.x * 8)
        acc += g_out2[(size_t)row * 32 + c];
    sred[threadIdx.x] = acc;
    __syncthreads();
    if (threadIdx.x < 32) {
        float s2 = 0.f;
#pragma unroll
        for (int g = 0; g < 8; g++) s2 += sred[g * 32 + threadIdx.x];
        atomicAdd(&g_pool[threadIdx.x], (double)s2);
    }
}

__global__ void k_final(const float* __restrict__ Wr, const float* __restrict__ br,
                        const float* __restrict__ b2, float* __restrict__ out) {
    if (threadIdx.x == 0) {
        double s = 0.0;
#pragma unroll
        for (int c = 0; c < 32; c++)
            s += (g_pool[c] + (double)N_NODES * (double)b2[c]) * (double)Wr[c];
        out[0] = (float)(s + (double)br[0]);
    }
}

// ---------------- launch ----------------
extern "C" void kernel_launch(void* const* d_in, const int* in_sizes, int n_in,
                              void* d_out, int out_size) {
    const float* x   = (const float*)d_in[0];
    const void*  ei  = d_in[1];
    const float* W1  = (const float*)d_in[2];
    const float* as1 = (const float*)d_in[3];
    const float* ad1 = (const float*)d_in[4];
    const float* b1  = (const float*)d_in[5];
    const float* W2  = (const float*)d_in[6];
    const float* as2 = (const float*)d_in[7];
    const float* ad2 = (const float*)d_in[8];
    const float* b2  = (const float*)d_in[9];
    const float* Wr  = (const float*)d_in[10];
    const float* br  = (const float*)d_in[11];
    float* out = (float*)d_out;

    int E = in_sizes[1] / 2;           // 3,200,000
    int Etot = E + N_NODES;            // +self loops
    int WPD = (N_NODES + 7) / 8;       // warp-per-dst grid (8 warps/block)

    k_detect<<<1, 256>>>((const int*)ei);
    k_init<<<(N_NODES + 255) / 256, 256>>>();
    k_edges<<<(Etot + 255) / 256, 256>>>(ei, E, Etot);
    k_scan1<<<NSCAN, SCAN_B>>>();
    k_scan2<<<1, 128>>>();
    k_scan3<<<(N_NODES + 255) / 256, 256>>>(Etot);
    k_scatter<<<(Etot + 255) / 256, 256>>>(Etot);
    k_gemm1<<<(N_NODES + 127) / 128, 256>>>(x, W1, as1, ad1);
    k_soft1<<<WPD, 256>>>();
    k_agg1c<<<WPD, 256>>>(b1);
    k_gemm2<<<N_NODES / 32, 256>>>(W2, as2, ad2);
    k_soft2<<<WPD, 256>>>();
    k_agg2c<<<WPD, 256>>>();
    k_pool<<<512, 256>>>();
    k_final<<<1, 32>>>(Wr, br, b2, out);
}